// round 4
// baseline (speedup 1.0000x reference)
#include <cuda_runtime.h>

// Problem constants
#define NB 4
#define NC 8
#define NF 512
#define NT 1000
#define NPAIR 36   // upper triangle incl diagonal of 8x8

struct SmemLayout {
    float2 xsh[NC * NT];   // [c*NT + t] = (re, im)
    float2 msk[NT];        // (mask_s, mask_n), raw then normalized in place
    float  bufr[2][NPAIR]; // [0]=psd_s real, [1]=psd_n real (packed upper tri)
    float  bufi[2][NPAIR];
    float2 A[64];          // psd_n_reg -> identity (Gauss-Jordan)
    float2 Bm[64];         // psd_s -> X = psd_n_reg^{-1} psd_s
    float2 G[64];          // G[m*8+c] = conj(W[c][m])
    float  sums[2];        // mask sums; sums[0] reused as diag regularizer
    float2 pivinv;
    float2 winv;
};

static __device__ __forceinline__ float2 cmul(float2 a, float2 b) {
    return make_float2(a.x * b.x - a.y * b.y, a.x * b.y + a.y * b.x);
}

template <bool COMPLEX_OUT>
__global__ __launch_bounds__(256, 2)
void pmwf_kernel(const float* __restrict__ xre, const float* __restrict__ xim,
                 const float* __restrict__ ms,  const float* __restrict__ mn,
                 float* __restrict__ out)
{
    extern __shared__ unsigned char smraw[];
    SmemLayout& sm = *reinterpret_cast<SmemLayout*>(smraw);
    const int tid = threadIdx.x;
    const int bf  = blockIdx.x;          // 0..NB*NF-1
    const int b   = bf / NF;
    const int f   = bf - b * NF;

    // ---- init small accumulators ----
    if (tid < NPAIR) {
        sm.bufr[0][tid] = 0.f; sm.bufi[0][tid] = 0.f;
        sm.bufr[1][tid] = 0.f; sm.bufi[1][tid] = 0.f;
    }
    if (tid == 64) { sm.sums[0] = 0.f; sm.sums[1] = 0.f; }

    // ---- load x tile (C x T complex) and masks into SMEM ----
    const long xbase = ((long)b * NC) * NF * NT + (long)f * NT;
    for (int idx = tid; idx < NC * NT; idx += 256) {
        int c = idx / NT;
        int t = idx - c * NT;
        long g = xbase + (long)c * NF * NT + t;
        sm.xsh[idx] = make_float2(__ldg(xre + g), __ldg(xim + g));
    }
    const long mbase = ((long)b * NF + f) * NT;
    for (int t = tid; t < NT; t += 256)
        sm.msk[t] = make_float2(__ldg(ms + mbase + t), __ldg(mn + mbase + t));
    __syncthreads();

    // ---- mask sums (block reduce) ----
    {
        float s0 = 0.f, s1 = 0.f;
        for (int t = tid; t < NT; t += 256) { float2 v = sm.msk[t]; s0 += v.x; s1 += v.y; }
        #pragma unroll
        for (int o = 16; o; o >>= 1) {
            s0 += __shfl_down_sync(0xffffffffu, s0, o);
            s1 += __shfl_down_sync(0xffffffffu, s1, o);
        }
        if ((tid & 31) == 0) { atomicAdd(&sm.sums[0], s0); atomicAdd(&sm.sums[1], s1); }
    }
    __syncthreads();
    {
        float i0 = 1.f / (sm.sums[0] + 1e-10f);
        float i1 = 1.f / (sm.sums[1] + 1e-10f);
        for (int t = tid; t < NT; t += 256) {
            float2 v = sm.msk[t]; v.x *= i0; v.y *= i1; sm.msk[t] = v;
        }
    }
    __syncthreads();

    // ---- PSD accumulation: threads 0-127 -> mask_s, 128-255 -> mask_n ----
    {
        const int role = tid >> 7;
        const int lt   = tid & 127;
        float ar[NPAIR], ai[NPAIR];
        #pragma unroll
        for (int p = 0; p < NPAIR; p++) { ar[p] = 0.f; ai[p] = 0.f; }

        for (int t = lt; t < NT; t += 128) {
            float2 xv[NC];
            #pragma unroll
            for (int c = 0; c < NC; c++) xv[c] = sm.xsh[c * NT + t];
            float2 mm = sm.msk[t];
            float m = role ? mm.y : mm.x;
            int p = 0;
            #pragma unroll
            for (int c = 0; c < NC; c++) {
                #pragma unroll
                for (int e = c; e < NC; e++) {
                    // x_c * conj(x_e)
                    float pr = xv[c].x * xv[e].x + xv[c].y * xv[e].y;
                    float pi = xv[c].y * xv[e].x - xv[c].x * xv[e].y;
                    ar[p] += m * pr;
                    ai[p] += m * pi;
                    p++;
                }
            }
        }
        // warp reduce then atomic into role buffer
        #pragma unroll
        for (int p = 0; p < NPAIR; p++) {
            #pragma unroll
            for (int o = 16; o; o >>= 1) {
                ar[p] += __shfl_down_sync(0xffffffffu, ar[p], o);
                ai[p] += __shfl_down_sync(0xffffffffu, ai[p], o);
            }
        }
        if ((tid & 31) == 0) {
            #pragma unroll
            for (int p = 0; p < NPAIR; p++) {
                atomicAdd(&sm.bufr[role][p], ar[p]);
                atomicAdd(&sm.bufi[role][p], ai[p]);
            }
        }
    }
    __syncthreads();

    // ---- diag regularizer d = 1e-6 * tr(psd_n).re + 1e-8 ----
    if (tid == 0) {
        float trn = 0.f;
        #pragma unroll
        for (int c = 0; c < NC; c++) trn += sm.bufr[1][8 * c - (c * (c - 1)) / 2];
        sm.sums[0] = 1e-6f * trn + 1e-8f;   // reuse as dreg
    }
    __syncthreads();

    // ---- build full Hermitian A (psd_n + d I) and Bm (psd_s) ----
    if (tid < 64) {
        int i = tid >> 3, j = tid & 7;
        int lo = i < j ? i : j;
        int hi = i < j ? j : i;
        int p = 8 * lo - (lo * (lo - 1)) / 2 + (hi - lo);
        float sgn = (i <= j) ? 1.f : -1.f;
        float2 an = make_float2(sm.bufr[1][p], sgn * sm.bufi[1][p]);
        float2 as = make_float2(sm.bufr[0][p], sgn * sm.bufi[0][p]);
        if (i == j) an.x += sm.sums[0];
        sm.A[tid]  = an;
        sm.Bm[tid] = as;
    }
    __syncthreads();

    // ---- Gauss-Jordan: A X = Bm  ->  Bm = X ----
    {
        int i = tid >> 3, j = tid & 7;
        for (int k = 0; k < 8; k++) {
            if (tid == 0) {
                float2 pv = sm.A[k * 8 + k];
                float d = pv.x * pv.x + pv.y * pv.y;
                sm.pivinv = make_float2(pv.x / d, -pv.y / d);
            }
            __syncthreads();
            if (tid < 64 && i == k) {
                float2 pin = sm.pivinv;
                sm.A[tid]  = cmul(sm.A[tid], pin);
                sm.Bm[tid] = cmul(sm.Bm[tid], pin);
            }
            __syncthreads();
            float2 fct, akj, bkj;
            bool act = (tid < 64) && (i != k);
            if (act) { fct = sm.A[i * 8 + k]; akj = sm.A[k * 8 + j]; bkj = sm.Bm[k * 8 + j]; }
            __syncthreads();
            if (act) {
                float2 a = sm.A[tid], bm = sm.Bm[tid];
                a.x  -= fct.x * akj.x - fct.y * akj.y;
                a.y  -= fct.x * akj.y + fct.y * akj.x;
                bm.x -= fct.x * bkj.x - fct.y * bkj.y;
                bm.y -= fct.x * bkj.y + fct.y * bkj.x;
                sm.A[tid] = a; sm.Bm[tid] = bm;
            }
            __syncthreads();
        }
    }

    // ---- W = X / (beta + tr X); G[m][c] = conj(W[c][m]) ----
    if (tid == 0) {
        float2 tr = make_float2(1.0f, 0.0f);  // beta = 1
        #pragma unroll
        for (int c = 0; c < NC; c++) { tr.x += sm.Bm[c * 8 + c].x; tr.y += sm.Bm[c * 8 + c].y; }
        float d = tr.x * tr.x + tr.y * tr.y;
        sm.winv = make_float2(tr.x / d, -tr.y / d);
    }
    __syncthreads();
    if (tid < 64) {
        int i = tid >> 3, j = tid & 7;  // i = c (row), j = m (col)
        float2 w = cmul(sm.Bm[tid], sm.winv);
        sm.G[j * 8 + i] = make_float2(w.x, -w.y);
    }
    __syncthreads();

    // ---- filter: out[m][t] = sum_c G[m][c] * x[c][t]; 4m x 4t register tiles ----
    const long obase = ((long)b * NC) * NF * NT + (long)f * NT;  // in output elements (per m-plane indexing below)
    for (int q = tid; q < 500; q += 256) {
        int mg = q / 250;
        int tg = q - mg * 250;
        int m0 = mg * 4, t0 = tg * 4;
        float2 acc[4][4];
        #pragma unroll
        for (int i = 0; i < 4; i++)
            #pragma unroll
            for (int j = 0; j < 4; j++) acc[i][j] = make_float2(0.f, 0.f);

        #pragma unroll
        for (int c = 0; c < NC; c++) {
            float2 xv[4];
            #pragma unroll
            for (int j = 0; j < 4; j++) xv[j] = sm.xsh[c * NT + t0 + j];
            #pragma unroll
            for (int i = 0; i < 4; i++) {
                float2 g = sm.G[(m0 + i) * 8 + c];
                #pragma unroll
                for (int j = 0; j < 4; j++) {
                    acc[i][j].x += g.x * xv[j].x - g.y * xv[j].y;
                    acc[i][j].y += g.x * xv[j].y + g.y * xv[j].x;
                }
            }
        }
        if (COMPLEX_OUT) {
            // interleaved complex64: (B,C,F,T) pairs of floats
            #pragma unroll
            for (int i = 0; i < 4; i++) {
                float2* op = reinterpret_cast<float2*>(out) + obase + (long)(m0 + i) * NF * NT + t0;
                float4* op4 = reinterpret_cast<float4*>(op);
                op4[0] = make_float4(acc[i][0].x, acc[i][0].y, acc[i][1].x, acc[i][1].y);
                op4[1] = make_float4(acc[i][2].x, acc[i][2].y, acc[i][3].x, acc[i][3].y);
            }
        } else {
            // real part only: (B,C,F,T) float32
            #pragma unroll
            for (int i = 0; i < 4; i++) {
                float* op = out + obase + (long)(m0 + i) * NF * NT + t0;
                float4* op4 = reinterpret_cast<float4*>(op);
                op4[0] = make_float4(acc[i][0].x, acc[i][1].x, acc[i][2].x, acc[i][3].x);
            }
        }
    }
}

extern "C" void kernel_launch(void* const* d_in, const int* in_sizes, int n_in,
                              void* d_out, int out_size) {
    (void)in_sizes; (void)n_in;
    const int nElem = NB * NC * NF * NT;           // 16,384,000
    const bool cplx = (out_size >= 2 * nElem);     // 32,768,000 floats => interleaved complex
    const int smem = (int)sizeof(SmemLayout);
    if (cplx) {
        cudaFuncSetAttribute(pmwf_kernel<true>, cudaFuncAttributeMaxDynamicSharedMemorySize, smem);
        pmwf_kernel<true><<<NB * NF, 256, smem>>>(
            (const float*)d_in[0], (const float*)d_in[1],
            (const float*)d_in[2], (const float*)d_in[3], (float*)d_out);
    } else {
        cudaFuncSetAttribute(pmwf_kernel<false>, cudaFuncAttributeMaxDynamicSharedMemorySize, smem);
        pmwf_kernel<false><<<NB * NF, 256, smem>>>(
            (const float*)d_in[0], (const float*)d_in[1],
            (const float*)d_in[2], (const float*)d_in[3], (float*)d_out);
    }
}

// round 5
// speedup vs baseline: 1.3973x; 1.3973x over previous
#include <cuda_runtime.h>

// Problem constants
#define NB 4
#define NC 8
#define NF 512
#define NT 1000
#define NPAIR 36   // upper triangle incl diagonal of 8x8

struct SmemLayout {
    float2 xsh[NC * NT];   // [c*NT + t] = (re, im)
    float2 msk[NT];        // (mask_s, mask_n) normalized
    float  bufr[2][NPAIR]; // [0]=psd_s real, [1]=psd_n real (packed upper tri)
    float  bufi[2][NPAIR];
    float2 A[64];          // psd_n_reg -> identity (Gauss-Jordan)
    float2 Bm[64];         // psd_s -> X = psd_n_reg^{-1} psd_s
    float2 G[64];          // G[m*8+c] = conj(W[c][m])
    float  sums[2];        // mask sums; sums[0] reused as diag regularizer
    float2 pivinv;
    float2 winv;
};

static __device__ __forceinline__ float2 cmul(float2 a, float2 b) {
    return make_float2(a.x * b.x - a.y * b.y, a.x * b.y + a.y * b.x);
}

static __device__ __forceinline__ float warp_reduce(float v) {
    #pragma unroll
    for (int o = 16; o; o >>= 1) v += __shfl_down_sync(0xffffffffu, v, o);
    return v;
}

// PSD accumulation for pair-group G: rows R0=G and R1=7-G of the upper
// triangle (always 9 pairs). Products shared between both mask roles.
// This warp covers t in [half*500, half*500+500) with 32 lanes.
template <int G>
static __device__ __forceinline__ void psd_group(SmemLayout& sm, int half, int lane) {
    constexpr int R0 = G;
    constexpr int R1 = 7 - G;
    constexpr int N0 = 8 - G;       // pairs in row R0: (R0, R0..7)
    constexpr int N1 = G + 1;       // pairs in row R1: (R1, R1..7)
    constexpr int NCH = 8 - G;      // channels R0..7 needed
    constexpr int BASE0 = 8 * R0 - (R0 * (R0 - 1)) / 2;
    constexpr int BASE1 = 8 * R1 - (R1 * (R1 - 1)) / 2;

    float aR[2][9], aI[2][9];
    #pragma unroll
    for (int k = 0; k < 9; k++) {
        aR[0][k] = 0.f; aR[1][k] = 0.f; aI[0][k] = 0.f; aI[1][k] = 0.f;
    }

    const int tb = half * 500;
    #pragma unroll 4
    for (int i = 0; i < 16; i++) {
        int tt = lane + (i << 5);
        if (tt < 500) {
            int t = tb + tt;
            float2 xv[NCH];
            #pragma unroll
            for (int j = 0; j < NCH; j++) xv[j] = sm.xsh[(R0 + j) * NT + t];
            float2 mm = sm.msk[t];

            float2 a0 = xv[0];                    // x_{R0}
            #pragma unroll
            for (int k = 0; k < N0; k++) {
                float2 bx = xv[k];                // x_{R0+k}
                float pr = a0.x * bx.x + a0.y * bx.y;
                float pi = a0.y * bx.x - a0.x * bx.y;
                aR[0][k] += mm.x * pr; aR[1][k] += mm.y * pr;
                aI[0][k] += mm.x * pi; aI[1][k] += mm.y * pi;
            }
            float2 a1 = xv[R1 - R0];              // x_{R1}
            #pragma unroll
            for (int k = 0; k < N1; k++) {
                float2 bx = xv[(R1 - R0) + k];    // x_{R1+k}
                float pr = a1.x * bx.x + a1.y * bx.y;
                float pi = a1.y * bx.x - a1.x * bx.y;
                aR[0][N0 + k] += mm.x * pr; aR[1][N0 + k] += mm.y * pr;
                aI[0][N0 + k] += mm.x * pi; aI[1][N0 + k] += mm.y * pi;
            }
        }
    }

    // warp-reduce all 36 scalars, lane 0 commits via smem atomics
    #pragma unroll
    for (int k = 0; k < 9; k++) {
        float r0 = warp_reduce(aR[0][k]);
        float r1 = warp_reduce(aR[1][k]);
        float i0 = warp_reduce(aI[0][k]);
        float i1 = warp_reduce(aI[1][k]);
        if (lane == 0) {
            int p = (k < N0) ? (BASE0 + k) : (BASE1 + (k - N0));
            atomicAdd(&sm.bufr[0][p], r0);
            atomicAdd(&sm.bufr[1][p], r1);
            atomicAdd(&sm.bufi[0][p], i0);
            atomicAdd(&sm.bufi[1][p], i1);
        }
    }
}

template <bool COMPLEX_OUT>
__global__ __launch_bounds__(256, 3)
void pmwf_kernel(const float* __restrict__ xre, const float* __restrict__ xim,
                 const float* __restrict__ ms,  const float* __restrict__ mn,
                 float* __restrict__ out)
{
    extern __shared__ unsigned char smraw[];
    SmemLayout& sm = *reinterpret_cast<SmemLayout*>(smraw);
    const int tid = threadIdx.x;
    const int bf  = blockIdx.x;          // 0..NB*NF-1
    const int b   = bf / NF;
    const int f   = bf - b * NF;

    // ---- init small accumulators ----
    if (tid < NPAIR) {
        sm.bufr[0][tid] = 0.f; sm.bufi[0][tid] = 0.f;
        sm.bufr[1][tid] = 0.f; sm.bufi[1][tid] = 0.f;
    }
    if (tid == 64) { sm.sums[0] = 0.f; sm.sums[1] = 0.f; }

    // ---- load x tile (C x T complex) via float4, interleave into SMEM ----
    const long xbase = ((long)b * NC) * NF * NT + (long)f * NT;
    for (int idx = tid; idx < NC * (NT / 4); idx += 256) {
        int c  = idx / (NT / 4);
        int t4 = (idx - c * (NT / 4)) * 4;
        long g = xbase + (long)c * NF * NT + t4;
        float4 r = *reinterpret_cast<const float4*>(xre + g);
        float4 im = *reinterpret_cast<const float4*>(xim + g);
        float4* dst = reinterpret_cast<float4*>(&sm.xsh[c * NT + t4]);
        dst[0] = make_float4(r.x, im.x, r.y, im.y);
        dst[1] = make_float4(r.z, im.z, r.w, im.w);
    }
    const long mbase = ((long)b * NF + f) * NT;
    for (int idx = tid; idx < NT / 4; idx += 256) {
        int t4 = idx * 4;
        float4 s = *reinterpret_cast<const float4*>(ms + mbase + t4);
        float4 n = *reinterpret_cast<const float4*>(mn + mbase + t4);
        float4* dst = reinterpret_cast<float4*>(&sm.msk[t4]);
        dst[0] = make_float4(s.x, n.x, s.y, n.y);
        dst[1] = make_float4(s.z, n.z, s.w, n.w);
    }
    __syncthreads();

    // ---- mask sums (block reduce) ----
    {
        float s0 = 0.f, s1 = 0.f;
        for (int t = tid; t < NT; t += 256) { float2 v = sm.msk[t]; s0 += v.x; s1 += v.y; }
        s0 = warp_reduce(s0);
        s1 = warp_reduce(s1);
        if ((tid & 31) == 0) { atomicAdd(&sm.sums[0], s0); atomicAdd(&sm.sums[1], s1); }
    }
    __syncthreads();
    {
        float i0 = 1.f / (sm.sums[0] + 1e-10f);
        float i1 = 1.f / (sm.sums[1] + 1e-10f);
        for (int t = tid; t < NT; t += 256) {
            float2 v = sm.msk[t]; v.x *= i0; v.y *= i1; sm.msk[t] = v;
        }
    }
    __syncthreads();

    // ---- PSD: 8 warps = 2 t-halves x 4 pair-groups; products shared across roles ----
    {
        const int w    = tid >> 5;
        const int lane = tid & 31;
        const int half = w & 1;
        const int pg   = w >> 1;
        switch (pg) {
            case 0: psd_group<0>(sm, half, lane); break;
            case 1: psd_group<1>(sm, half, lane); break;
            case 2: psd_group<2>(sm, half, lane); break;
            default: psd_group<3>(sm, half, lane); break;
        }
    }
    __syncthreads();

    // ---- diag regularizer d = 1e-6 * tr(psd_n).re + 1e-8 ----
    if (tid == 0) {
        float trn = 0.f;
        #pragma unroll
        for (int c = 0; c < NC; c++) trn += sm.bufr[1][8 * c - (c * (c - 1)) / 2];
        sm.sums[0] = 1e-6f * trn + 1e-8f;   // reuse as dreg
    }
    __syncthreads();

    // ---- build full Hermitian A (psd_n + d I) and Bm (psd_s) ----
    if (tid < 64) {
        int i = tid >> 3, j = tid & 7;
        int lo = i < j ? i : j;
        int hi = i < j ? j : i;
        int p = 8 * lo - (lo * (lo - 1)) / 2 + (hi - lo);
        float sgn = (i <= j) ? 1.f : -1.f;
        float2 an = make_float2(sm.bufr[1][p], sgn * sm.bufi[1][p]);
        float2 as = make_float2(sm.bufr[0][p], sgn * sm.bufi[0][p]);
        if (i == j) an.x += sm.sums[0];
        sm.A[tid]  = an;
        sm.Bm[tid] = as;
    }
    __syncthreads();

    // ---- Gauss-Jordan: A X = Bm  ->  Bm = X ----
    {
        int i = tid >> 3, j = tid & 7;
        for (int k = 0; k < 8; k++) {
            if (tid == 0) {
                float2 pv = sm.A[k * 8 + k];
                float d = pv.x * pv.x + pv.y * pv.y;
                sm.pivinv = make_float2(pv.x / d, -pv.y / d);
            }
            __syncthreads();
            if (tid < 64 && i == k) {
                float2 pin = sm.pivinv;
                sm.A[tid]  = cmul(sm.A[tid], pin);
                sm.Bm[tid] = cmul(sm.Bm[tid], pin);
            }
            __syncthreads();
            float2 fct, akj, bkj;
            bool act = (tid < 64) && (i != k);
            if (act) { fct = sm.A[i * 8 + k]; akj = sm.A[k * 8 + j]; bkj = sm.Bm[k * 8 + j]; }
            __syncthreads();
            if (act) {
                float2 a = sm.A[tid], bm = sm.Bm[tid];
                a.x  -= fct.x * akj.x - fct.y * akj.y;
                a.y  -= fct.x * akj.y + fct.y * akj.x;
                bm.x -= fct.x * bkj.x - fct.y * bkj.y;
                bm.y -= fct.x * bkj.y + fct.y * bkj.x;
                sm.A[tid] = a; sm.Bm[tid] = bm;
            }
            __syncthreads();
        }
    }

    // ---- W = X / (beta + tr X); G[m][c] = conj(W[c][m]) ----
    if (tid == 0) {
        float2 tr = make_float2(1.0f, 0.0f);  // beta = 1
        #pragma unroll
        for (int c = 0; c < NC; c++) { tr.x += sm.Bm[c * 8 + c].x; tr.y += sm.Bm[c * 8 + c].y; }
        float d = tr.x * tr.x + tr.y * tr.y;
        sm.winv = make_float2(tr.x / d, -tr.y / d);
    }
    __syncthreads();
    if (tid < 64) {
        int i = tid >> 3, j = tid & 7;  // i = c (row), j = m (col)
        float2 w = cmul(sm.Bm[tid], sm.winv);
        sm.G[j * 8 + i] = make_float2(w.x, -w.y);
    }
    __syncthreads();

    // ---- filter: out[m][t] = sum_c G[m][c] * x[c][t]; 4m x 4t tiles ----
    const long obase = ((long)b * NC) * NF * NT + (long)f * NT;
    for (int q = tid; q < 500; q += 256) {
        int mg = q / 250;
        int tg = q - mg * 250;
        int m0 = mg * 4, t0 = tg * 4;

        if (COMPLEX_OUT) {
            float2 acc[4][4];
            #pragma unroll
            for (int i = 0; i < 4; i++)
                #pragma unroll
                for (int j = 0; j < 4; j++) acc[i][j] = make_float2(0.f, 0.f);
            #pragma unroll
            for (int c = 0; c < NC; c++) {
                const float4* xp = reinterpret_cast<const float4*>(&sm.xsh[c * NT + t0]);
                float4 v0 = xp[0], v1 = xp[1];
                float2 xv[4] = { {v0.x, v0.y}, {v0.z, v0.w}, {v1.x, v1.y}, {v1.z, v1.w} };
                #pragma unroll
                for (int i = 0; i < 4; i++) {
                    float2 g = sm.G[(m0 + i) * 8 + c];
                    #pragma unroll
                    for (int j = 0; j < 4; j++) {
                        acc[i][j].x += g.x * xv[j].x - g.y * xv[j].y;
                        acc[i][j].y += g.x * xv[j].y + g.y * xv[j].x;
                    }
                }
            }
            #pragma unroll
            for (int i = 0; i < 4; i++) {
                float2* op = reinterpret_cast<float2*>(out) + obase + (long)(m0 + i) * NF * NT + t0;
                float4* op4 = reinterpret_cast<float4*>(op);
                op4[0] = make_float4(acc[i][0].x, acc[i][0].y, acc[i][1].x, acc[i][1].y);
                op4[1] = make_float4(acc[i][2].x, acc[i][2].y, acc[i][3].x, acc[i][3].y);
            }
        } else {
            // real part only: 2 FMA per channel per element
            float acc[4][4];
            #pragma unroll
            for (int i = 0; i < 4; i++)
                #pragma unroll
                for (int j = 0; j < 4; j++) acc[i][j] = 0.f;
            #pragma unroll
            for (int c = 0; c < NC; c++) {
                const float4* xp = reinterpret_cast<const float4*>(&sm.xsh[c * NT + t0]);
                float4 v0 = xp[0], v1 = xp[1];
                float2 xv[4] = { {v0.x, v0.y}, {v0.z, v0.w}, {v1.x, v1.y}, {v1.z, v1.w} };
                #pragma unroll
                for (int i = 0; i < 4; i++) {
                    float2 g = sm.G[(m0 + i) * 8 + c];
                    #pragma unroll
                    for (int j = 0; j < 4; j++)
                        acc[i][j] += g.x * xv[j].x - g.y * xv[j].y;
                }
            }
            #pragma unroll
            for (int i = 0; i < 4; i++) {
                float* op = out + obase + (long)(m0 + i) * NF * NT + t0;
                *reinterpret_cast<float4*>(op) =
                    make_float4(acc[i][0], acc[i][1], acc[i][2], acc[i][3]);
            }
        }
    }
}

extern "C" void kernel_launch(void* const* d_in, const int* in_sizes, int n_in,
                              void* d_out, int out_size) {
    (void)in_sizes; (void)n_in;
    const int nElem = NB * NC * NF * NT;           // 16,384,000
    const bool cplx = (out_size >= 2 * nElem);     // interleaved complex if doubled
    const int smem = (int)sizeof(SmemLayout);
    if (cplx) {
        cudaFuncSetAttribute(pmwf_kernel<true>, cudaFuncAttributeMaxDynamicSharedMemorySize, smem);
        pmwf_kernel<true><<<NB * NF, 256, smem>>>(
            (const float*)d_in[0], (const float*)d_in[1],
            (const float*)d_in[2], (const float*)d_in[3], (float*)d_out);
    } else {
        cudaFuncSetAttribute(pmwf_kernel<false>, cudaFuncAttributeMaxDynamicSharedMemorySize, smem);
        pmwf_kernel<false><<<NB * NF, 256, smem>>>(
            (const float*)d_in[0], (const float*)d_in[1],
            (const float*)d_in[2], (const float*)d_in[3], (float*)d_out);
    }
}